// round 1
// baseline (speedup 1.0000x reference)
#include <cuda_runtime.h>
#include <cstdint>

// Problem shapes (fixed by the dataset)
#define M_DIM 8192
#define K_DIM 4096
#define N_DIM 4096
#define KB    32          // K / 128
#define NB    32          // N / 128

// ---------------------------------------------------------------------------
// Scratch (no cudaMalloc allowed): quantized tensors + scales as device globals
// ---------------------------------------------------------------------------
__device__ __align__(16) signed char g_xq[(size_t)M_DIM * K_DIM];   // 33.5 MB
__device__ float                     g_xs[(size_t)M_DIM * KB];      // 1 MB
__device__ __align__(16) signed char g_wq[(size_t)N_DIM * K_DIM];   // 16.8 MB
__device__ float                     g_ws[NB * KB];                 // 4 KB

// ---------------------------------------------------------------------------
// Kernel 1: activation quant. One warp per (m, kb) 128-wide block.
// s = max|x|/127 (true IEEE div, clamp 1e-12); q = clip(rint(x/s), -128, 127)
// ---------------------------------------------------------------------------
__global__ void quant_x_kernel(const float* __restrict__ x) {
    int gw   = (blockIdx.x * blockDim.x + threadIdx.x) >> 5;  // global warp id
    int lane = threadIdx.x & 31;
    int m  = gw >> 5;        // KB = 32 blocks per row
    int kb = gw & 31;

    const float4* p = reinterpret_cast<const float4*>(x + (size_t)m * K_DIM + kb * 128);
    float4 v = p[lane];
    float a = fmaxf(fmaxf(fabsf(v.x), fabsf(v.y)), fmaxf(fabsf(v.z), fabsf(v.w)));
    #pragma unroll
    for (int off = 16; off > 0; off >>= 1)
        a = fmaxf(a, __shfl_xor_sync(0xffffffffu, a, off));

    float s = fmaxf(__fdiv_rn(a, 127.0f), 1e-12f);

    char4 q;
    q.x = (signed char)(int)fminf(fmaxf(rintf(__fdiv_rn(v.x, s)), -128.0f), 127.0f);
    q.y = (signed char)(int)fminf(fmaxf(rintf(__fdiv_rn(v.y, s)), -128.0f), 127.0f);
    q.z = (signed char)(int)fminf(fmaxf(rintf(__fdiv_rn(v.z, s)), -128.0f), 127.0f);
    q.w = (signed char)(int)fminf(fmaxf(rintf(__fdiv_rn(v.w, s)), -128.0f), 127.0f);

    reinterpret_cast<char4*>(g_xq + (size_t)m * K_DIM + kb * 128)[lane] = q;
    if (lane == 0) g_xs[m * KB + kb] = s;
}

// ---------------------------------------------------------------------------
// Kernel 2: weight quant. One 256-thread CTA per (nb, kb) 128x128 block.
// Values held in registers (64 floats/thread) to avoid a second global read.
// ---------------------------------------------------------------------------
__global__ void quant_w_kernel(const float* __restrict__ w) {
    int nb = blockIdx.x >> 5;
    int kb = blockIdx.x & 31;
    int t    = threadIdx.x;
    int row  = t >> 1;           // 0..127
    int half = t & 1;            // each thread owns 16 float4 = 64 floats

    const float4* p = reinterpret_cast<const float4*>(
        w + (size_t)(nb * 128 + row) * K_DIM + kb * 128) + half * 16;

    float4 vv[16];
    float a = 0.0f;
    #pragma unroll
    for (int i = 0; i < 16; i++) {
        vv[i] = p[i];
        a = fmaxf(a, fmaxf(fmaxf(fabsf(vv[i].x), fabsf(vv[i].y)),
                           fmaxf(fabsf(vv[i].z), fabsf(vv[i].w))));
    }
    // block-wide amax
    #pragma unroll
    for (int off = 16; off > 0; off >>= 1)
        a = fmaxf(a, __shfl_xor_sync(0xffffffffu, a, off));
    __shared__ float red[8];
    if ((t & 31) == 0) red[t >> 5] = a;
    __syncthreads();
    float am = red[0];
    #pragma unroll
    for (int i = 1; i < 8; i++) am = fmaxf(am, red[i]);

    float s = fmaxf(__fdiv_rn(am, 127.0f), 1e-12f);

    char4* q = reinterpret_cast<char4*>(
        g_wq + (size_t)(nb * 128 + row) * K_DIM + kb * 128) + half * 16;
    #pragma unroll
    for (int i = 0; i < 16; i++) {
        char4 c;
        c.x = (signed char)(int)fminf(fmaxf(rintf(__fdiv_rn(vv[i].x, s)), -128.0f), 127.0f);
        c.y = (signed char)(int)fminf(fmaxf(rintf(__fdiv_rn(vv[i].y, s)), -128.0f), 127.0f);
        c.z = (signed char)(int)fminf(fmaxf(rintf(__fdiv_rn(vv[i].z, s)), -128.0f), 127.0f);
        c.w = (signed char)(int)fminf(fmaxf(rintf(__fdiv_rn(vv[i].w, s)), -128.0f), 127.0f);
        q[i] = c;
    }
    if (t == 0) g_ws[nb * KB + kb] = s;
}

// ---------------------------------------------------------------------------
// Kernel 3: int8 GEMM, 128x128 CTA tile, K-step 128 (= one scale block),
// mma.sync.m16n8k32.s8 with s32 register accumulators, per-kb fp32 promotion.
// ---------------------------------------------------------------------------
#define ROWB   144                       // 128-byte row + 16B pad (bank-conflict-free)
#define BUFSZ  (128 * ROWB)              // 18432 bytes per tile buffer
#define SMEMSZ (4 * BUFSZ)               // A[2] + B[2] = 73728 bytes

__device__ __forceinline__ void cpasync16(void* s, const void* g) {
    uint32_t sa = (uint32_t)__cvta_generic_to_shared(s);
    asm volatile("cp.async.cg.shared.global [%0], [%1], 16;\n" :: "r"(sa), "l"(g));
}
__device__ __forceinline__ void cp_commit() { asm volatile("cp.async.commit_group;\n"); }
__device__ __forceinline__ void cp_wait1()  { asm volatile("cp.async.wait_group 1;\n"); }

__device__ __forceinline__ void mma_s8(int c[4], const uint32_t a[4], const uint32_t b[2]) {
    asm volatile(
        "mma.sync.aligned.m16n8k32.row.col.s32.s8.s8.s32 "
        "{%0,%1,%2,%3}, {%4,%5,%6,%7}, {%8,%9}, {%0,%1,%2,%3};\n"
        : "+r"(c[0]), "+r"(c[1]), "+r"(c[2]), "+r"(c[3])
        : "r"(a[0]), "r"(a[1]), "r"(a[2]), "r"(a[3]), "r"(b[0]), "r"(b[1]));
}

// exact int32 -> float for |v| < 2^22, avoiding the cvt pipe
__device__ __forceinline__ float s32_to_f32(int v) {
    return __int_as_float(0x4B400000 + v) - 12582912.0f;
}

__device__ __forceinline__ void load_tile(char* As, char* Bs, int buf,
                                          int m0, int n0, int kb, int tid) {
    #pragma unroll
    for (int i = 0; i < 4; i++) {
        int id = i * 256 + tid;       // 0..1023 chunks of 16B
        int r  = id >> 3;
        int c  = id & 7;
        cpasync16(As + buf * BUFSZ + r * ROWB + c * 16,
                  g_xq + (size_t)(m0 + r) * K_DIM + kb * 128 + c * 16);
    }
    #pragma unroll
    for (int i = 0; i < 4; i++) {
        int id = i * 256 + tid;
        int r  = id >> 3;
        int c  = id & 7;
        cpasync16(Bs + buf * BUFSZ + r * ROWB + c * 16,
                  g_wq + (size_t)(n0 + r) * K_DIM + kb * 128 + c * 16);
    }
}

__global__ void __launch_bounds__(256, 1)
gemm_kernel(const float* __restrict__ bias, float* __restrict__ out) {
    extern __shared__ char smem[];
    char* As = smem;
    char* Bs = smem + 2 * BUFSZ;

    const int m0 = blockIdx.y * 128;
    const int n0 = blockIdx.x * 128;
    const int nb = blockIdx.x;
    const int tid  = threadIdx.x;
    const int lane = tid & 31;
    const int w    = tid >> 5;
    const int wm   = w & 3;        // 4 warps along M (32 rows each)
    const int wn   = w >> 2;       // 2 warps along N (64 cols each)
    const int grp  = lane >> 2;    // 0..7
    const int tig  = lane & 3;     // 0..3

    float facc[2][8][4];
    #pragma unroll
    for (int i = 0; i < 2; i++)
        #pragma unroll
        for (int j = 0; j < 8; j++)
            #pragma unroll
            for (int k = 0; k < 4; k++) facc[i][j][k] = 0.0f;

    load_tile(As, Bs, 0, m0, n0, 0, tid); cp_commit();
    load_tile(As, Bs, 1, m0, n0, 1, tid); cp_commit();

    for (int kb = 0; kb < KB; kb++) {
        cp_wait1();
        __syncthreads();
        const int buf = kb & 1;
        const char* Ab = As + buf * BUFSZ;
        const char* Bb = Bs + buf * BUFSZ;

        int c[2][8][4];
        #pragma unroll
        for (int i = 0; i < 2; i++)
            #pragma unroll
            for (int j = 0; j < 8; j++)
                #pragma unroll
                for (int k = 0; k < 4; k++) c[i][j][k] = 0;

        #pragma unroll
        for (int kk = 0; kk < 4; kk++) {
            const int k0 = kk * 32 + tig * 4;
            uint32_t a[2][4];
            #pragma unroll
            for (int fm = 0; fm < 2; fm++) {
                int r = wm * 32 + fm * 16 + grp;
                a[fm][0] = *(const uint32_t*)(Ab + r * ROWB + k0);
                a[fm][1] = *(const uint32_t*)(Ab + (r + 8) * ROWB + k0);
                a[fm][2] = *(const uint32_t*)(Ab + r * ROWB + k0 + 16);
                a[fm][3] = *(const uint32_t*)(Ab + (r + 8) * ROWB + k0 + 16);
            }
            uint32_t bf[8][2];
            #pragma unroll
            for (int fn = 0; fn < 8; fn++) {
                int cn = wn * 64 + fn * 8 + grp;
                bf[fn][0] = *(const uint32_t*)(Bb + cn * ROWB + k0);
                bf[fn][1] = *(const uint32_t*)(Bb + cn * ROWB + k0 + 16);
            }
            #pragma unroll
            for (int fm = 0; fm < 2; fm++)
                #pragma unroll
                for (int fn = 0; fn < 8; fn++)
                    mma_s8(c[fm][fn], a[fm], bf[fn]);
        }

        // per-kb exact promotion into fp32 accumulators
        const float wsv = g_ws[nb * KB + kb];
        #pragma unroll
        for (int fm = 0; fm < 2; fm++) {
            int r = m0 + wm * 32 + fm * 16 + grp;
            float cs0 = __ldg(&g_xs[(size_t)r * KB + kb]) * wsv;
            float cs1 = __ldg(&g_xs[(size_t)(r + 8) * KB + kb]) * wsv;
            #pragma unroll
            for (int fn = 0; fn < 8; fn++) {
                facc[fm][fn][0] += cs0 * s32_to_f32(c[fm][fn][0]);
                facc[fm][fn][1] += cs0 * s32_to_f32(c[fm][fn][1]);
                facc[fm][fn][2] += cs1 * s32_to_f32(c[fm][fn][2]);
                facc[fm][fn][3] += cs1 * s32_to_f32(c[fm][fn][3]);
            }
        }

        __syncthreads();
        if (kb + 2 < KB) load_tile(As, Bs, buf, m0, n0, kb + 2, tid);
        cp_commit();   // empty groups at the tail keep wait_group accounting simple
    }

    // epilogue: add bias, store fp32
    #pragma unroll
    for (int fm = 0; fm < 2; fm++) {
        int r = m0 + wm * 32 + fm * 16 + grp;
        #pragma unroll
        for (int fn = 0; fn < 8; fn++) {
            int cc = n0 + wn * 64 + fn * 8 + tig * 2;
            float2 b2 = *reinterpret_cast<const float2*>(bias + cc);
            float2 o0, o1;
            o0.x = facc[fm][fn][0] + b2.x;
            o0.y = facc[fm][fn][1] + b2.y;
            o1.x = facc[fm][fn][2] + b2.x;
            o1.y = facc[fm][fn][3] + b2.y;
            *reinterpret_cast<float2*>(out + (size_t)r * N_DIM + cc)       = o0;
            *reinterpret_cast<float2*>(out + (size_t)(r + 8) * N_DIM + cc) = o1;
        }
    }
}

// ---------------------------------------------------------------------------
extern "C" void kernel_launch(void* const* d_in, const int* in_sizes, int n_in,
                              void* d_out, int out_size) {
    const float* x    = (const float*)d_in[0];
    const float* wgt  = (const float*)d_in[1];
    const float* bias = (const float*)d_in[2];
    float* out        = (float*)d_out;

    // 8 blocks-per-row * 32 kb * 8192 rows / 8 warps = 32768 CTAs
    quant_x_kernel<<<(M_DIM * KB) / 8, 256>>>(x);
    quant_w_kernel<<<NB * KB, 256>>>(wgt);

    cudaFuncSetAttribute(gemm_kernel,
                         cudaFuncAttributeMaxDynamicSharedMemorySize, SMEMSZ);
    dim3 grid(N_DIM / 128, M_DIM / 128);
    gemm_kernel<<<grid, 256, SMEMSZ>>>(bias, out);
}

// round 3
// speedup vs baseline: 1.0905x; 1.0905x over previous
#include <cuda_runtime.h>
#include <cstdint>

// Problem shapes (fixed by the dataset)
#define M_DIM 8192
#define K_DIM 4096
#define N_DIM 4096
#define KB    32          // K / 128
#define NB    32          // N / 128

// ---------------------------------------------------------------------------
// Scratch (no cudaMalloc allowed)
// ---------------------------------------------------------------------------
__device__ __align__(16) signed char g_xq[(size_t)M_DIM * K_DIM];   // 33.5 MB
__device__ float                     g_xs[(size_t)KB * M_DIM];      // 1 MB ([kb][m])
__device__ __align__(16) signed char g_wq[(size_t)N_DIM * K_DIM];   // 16.8 MB
__device__ float                     g_ws[NB * KB];                 // 4 KB

// ---------------------------------------------------------------------------
// Kernel 1: activation quant. One warp per (m, kb) 128-wide block.
// ---------------------------------------------------------------------------
__global__ void quant_x_kernel(const float* __restrict__ x) {
    int gw   = (blockIdx.x * blockDim.x + threadIdx.x) >> 5;
    int lane = threadIdx.x & 31;
    int m  = gw >> 5;
    int kb = gw & 31;

    const float4* p = reinterpret_cast<const float4*>(x + (size_t)m * K_DIM + kb * 128);
    float4 v = p[lane];
    float a = fmaxf(fmaxf(fabsf(v.x), fabsf(v.y)), fmaxf(fabsf(v.z), fabsf(v.w)));
    #pragma unroll
    for (int off = 16; off > 0; off >>= 1)
        a = fmaxf(a, __shfl_xor_sync(0xffffffffu, a, off));

    float s = fmaxf(__fdiv_rn(a, 127.0f), 1e-12f);

    char4 q;
    q.x = (signed char)(int)fminf(fmaxf(rintf(__fdiv_rn(v.x, s)), -128.0f), 127.0f);
    q.y = (signed char)(int)fminf(fmaxf(rintf(__fdiv_rn(v.y, s)), -128.0f), 127.0f);
    q.z = (signed char)(int)fminf(fmaxf(rintf(__fdiv_rn(v.z, s)), -128.0f), 127.0f);
    q.w = (signed char)(int)fminf(fmaxf(rintf(__fdiv_rn(v.w, s)), -128.0f), 127.0f);

    reinterpret_cast<char4*>(g_xq + (size_t)m * K_DIM + kb * 128)[lane] = q;
    if (lane == 0) g_xs[(size_t)kb * M_DIM + m] = s;   // transposed for GEMM reads
}

// ---------------------------------------------------------------------------
// Kernel 2: weight quant. One 256-thread CTA per (nb, kb) 128x128 block.
// ---------------------------------------------------------------------------
__global__ void quant_w_kernel(const float* __restrict__ w) {
    int nb = blockIdx.x >> 5;
    int kb = blockIdx.x & 31;
    int t    = threadIdx.x;
    int row  = t >> 1;
    int half = t & 1;

    const float4* p = reinterpret_cast<const float4*>(
        w + (size_t)(nb * 128 + row) * K_DIM + kb * 128) + half * 16;

    float4 vv[16];
    float a = 0.0f;
    #pragma unroll
    for (int i = 0; i < 16; i++) {
        vv[i] = p[i];
        a = fmaxf(a, fmaxf(fmaxf(fabsf(vv[i].x), fabsf(vv[i].y)),
                           fmaxf(fabsf(vv[i].z), fabsf(vv[i].w))));
    }
    #pragma unroll
    for (int off = 16; off > 0; off >>= 1)
        a = fmaxf(a, __shfl_xor_sync(0xffffffffu, a, off));
    __shared__ float red[8];
    if ((t & 31) == 0) red[t >> 5] = a;
    __syncthreads();
    float am = red[0];
    #pragma unroll
    for (int i = 1; i < 8; i++) am = fmaxf(am, red[i]);

    float s = fmaxf(__fdiv_rn(am, 127.0f), 1e-12f);

    char4* q = reinterpret_cast<char4*>(
        g_wq + (size_t)(nb * 128 + row) * K_DIM + kb * 128) + half * 16;
    #pragma unroll
    for (int i = 0; i < 16; i++) {
        char4 c;
        c.x = (signed char)(int)fminf(fmaxf(rintf(__fdiv_rn(vv[i].x, s)), -128.0f), 127.0f);
        c.y = (signed char)(int)fminf(fmaxf(rintf(__fdiv_rn(vv[i].y, s)), -128.0f), 127.0f);
        c.z = (signed char)(int)fminf(fmaxf(rintf(__fdiv_rn(vv[i].z, s)), -128.0f), 127.0f);
        c.w = (signed char)(int)fminf(fmaxf(rintf(__fdiv_rn(vv[i].w, s)), -128.0f), 127.0f);
        q[i] = c;
    }
    if (t == 0) g_ws[nb * KB + kb] = s;
}

// ---------------------------------------------------------------------------
// Kernel 3: int8 GEMM. 128x128 CTA tile, K-step 128 (= one scale block),
// mma.sync.m16n8k32.s8 fed by ldmatrix.x4 on SW128-swizzled tiles.
// fn-pair-blocked s32 accumulation with exact per-kb fp32 promotion.
// ---------------------------------------------------------------------------
#define STAGES     4
#define TILE_BYTES 16384                       // 128 rows x 128 B, swizzled
#define SMEM_BOFF  (STAGES * TILE_BYTES)       // 65536
#define GEMM_SMEM  (2 * STAGES * TILE_BYTES)   // 131072

__device__ __forceinline__ uint32_t smem_u32(const void* p) {
    return (uint32_t)__cvta_generic_to_shared(p);
}
__device__ __forceinline__ void cpa16(uint32_t s, const void* g) {
    asm volatile("cp.async.cg.shared.global [%0], [%1], 16;\n" :: "r"(s), "l"(g));
}
__device__ __forceinline__ void mma_s8(int c[4], const uint32_t a[4], const uint32_t b[2]) {
    asm volatile(
        "mma.sync.aligned.m16n8k32.row.col.s32.s8.s8.s32 "
        "{%0,%1,%2,%3}, {%4,%5,%6,%7}, {%8,%9}, {%0,%1,%2,%3};\n"
        : "+r"(c[0]), "+r"(c[1]), "+r"(c[2]), "+r"(c[3])
        : "r"(a[0]), "r"(a[1]), "r"(a[2]), "r"(a[3]), "r"(b[0]), "r"(b[1]));
}
__device__ __forceinline__ void ldsm4(uint32_t r[4], uint32_t addr) {
    asm volatile("ldmatrix.sync.aligned.m8n8.x4.shared.b16 {%0,%1,%2,%3}, [%4];"
                 : "=r"(r[0]), "=r"(r[1]), "=r"(r[2]), "=r"(r[3]) : "r"(addr));
}

__global__ void __launch_bounds__(256, 1)
gemm_kernel(const float* __restrict__ bias, float* __restrict__ out) {
    extern __shared__ __align__(1024) char smem[];
    const uint32_t sb = smem_u32(smem);
    const int tid  = threadIdx.x;
    const int lane = tid & 31;
    const int w    = tid >> 5;
    const int m0 = blockIdx.y * 128;
    const int n0 = blockIdx.x * 128;
    const int nb = blockIdx.x;
    const int wm   = w & 3;        // 4 warps along M (32 rows each)
    const int wn   = w >> 2;       // 2 warps along N (64 cols each)
    const int grp  = lane >> 2;    // 0..7
    const int tig  = lane & 3;     // 0..3
    const int j    = lane >> 3;    // ldmatrix matrix index 0..3
    const int rlo  = lane & 7;     // ldmatrix row-in-matrix

    // tile loader: A + B 128x128B into stage, SW128-swizzled K-major
    auto load_stage = [&](int stage, int kb) {
        const signed char* Ag = g_xq + (size_t)m0 * K_DIM + kb * 128;
        const signed char* Bg = g_wq + (size_t)n0 * K_DIM + kb * 128;
        uint32_t As = sb + stage * TILE_BYTES;
        uint32_t Bs = sb + SMEM_BOFF + stage * TILE_BYTES;
        #pragma unroll
        for (int i = 0; i < 4; i++) {
            int id = i * 256 + tid;
            int r  = id >> 3;
            int c  = id & 7;
            uint32_t so = r * 128 + ((c ^ (r & 7)) << 4);
            cpa16(As + so, Ag + (size_t)r * K_DIM + c * 16);
            cpa16(Bs + so, Bg + (size_t)r * K_DIM + c * 16);
        }
    };

    float facc[2][8][4];
    #pragma unroll
    for (int i = 0; i < 2; i++)
        #pragma unroll
        for (int jj = 0; jj < 8; jj++)
            #pragma unroll
            for (int k = 0; k < 4; k++) facc[i][jj][k] = 0.0f;

    #pragma unroll
    for (int s = 0; s < 3; s++) {
        load_stage(s, s);
        asm volatile("cp.async.commit_group;");
    }

    for (int kb = 0; kb < KB; kb++) {
        asm volatile("cp.async.wait_group 2;");
        __syncthreads();
        const uint32_t As = sb + (uint32_t)(kb & 3) * TILE_BYTES;
        const uint32_t Bs = sb + SMEM_BOFF + (uint32_t)(kb & 3) * TILE_BYTES;

        // per-kb combined scales for this thread's 4 output rows
        const float wsv = g_ws[nb * KB + kb];
        float csv[2][2];
        #pragma unroll
        for (int fm = 0; fm < 2; fm++) {
            int r = m0 + wm * 32 + fm * 16 + grp;
            csv[fm][0] = __ldg(&g_xs[(size_t)kb * M_DIM + r])     * wsv;
            csv[fm][1] = __ldg(&g_xs[(size_t)kb * M_DIM + r + 8]) * wsv;
        }

        // A fragments for the whole k-block: 8 x ldmatrix.x4 -> 32 regs
        uint32_t a[2][4][4];
        #pragma unroll
        for (int fm = 0; fm < 2; fm++) {
            #pragma unroll
            for (int kk = 0; kk < 4; kk++) {
                int row   = wm * 32 + fm * 16 + rlo + ((j & 1) << 3);
                int chunk = kk * 2 + (j >> 1);
                ldsm4(a[fm][kk], As + row * 128 + ((chunk ^ (row & 7)) << 4));
            }
        }

        // fn-pair blocks: 16 s32 accumulators live at a time
        #pragma unroll
        for (int fnp = 0; fnp < 4; fnp++) {
            int c[2][2][4];
            #pragma unroll
            for (int i = 0; i < 2; i++)
                #pragma unroll
                for (int nt = 0; nt < 2; nt++)
                    #pragma unroll
                    for (int k = 0; k < 4; k++) c[i][nt][k] = 0;

            #pragma unroll
            for (int kk = 0; kk < 4; kk++) {
                int rown  = wn * 64 + fnp * 16 + ((j >> 1) << 3) + rlo;
                int chunk = kk * 2 + (j & 1);
                uint32_t bf[4];
                ldsm4(bf, Bs + rown * 128 + ((chunk ^ (rown & 7)) << 4));
                #pragma unroll
                for (int fm = 0; fm < 2; fm++) {
                    mma_s8(c[fm][0], a[fm][kk], bf);
                    mma_s8(c[fm][1], a[fm][kk], bf + 2);
                }
            }

            // exact promotion: |S| < 2^22 so int2float is exact
            #pragma unroll
            for (int fm = 0; fm < 2; fm++)
                #pragma unroll
                for (int nt = 0; nt < 2; nt++) {
                    float* f = facc[fm][fnp * 2 + nt];
                    f[0] = fmaf(csv[fm][0], __int2float_rn(c[fm][nt][0]), f[0]);
                    f[1] = fmaf(csv[fm][0], __int2float_rn(c[fm][nt][1]), f[1]);
                    f[2] = fmaf(csv[fm][1], __int2float_rn(c[fm][nt][2]), f[2]);
                    f[3] = fmaf(csv[fm][1], __int2float_rn(c[fm][nt][3]), f[3]);
                }
        }

        if (kb + 3 < KB) load_stage((kb + 3) & 3, kb + 3);
        asm volatile("cp.async.commit_group;");
    }

    // epilogue: add bias, store fp32
    #pragma unroll
    for (int fm = 0; fm < 2; fm++) {
        int r = m0 + wm * 32 + fm * 16 + grp;
        #pragma unroll
        for (int fn = 0; fn < 8; fn++) {
            int cc = n0 + wn * 64 + fn * 8 + tig * 2;
            float2 b2 = *reinterpret_cast<const float2*>(bias + cc);
            float2 o0, o1;
            o0.x = facc[fm][fn][0] + b2.x;
            o0.y = facc[fm][fn][1] + b2.y;
            o1.x = facc[fm][fn][2] + b2.x;
            o1.y = facc[fm][fn][3] + b2.y;
            *reinterpret_cast<float2*>(out + (size_t)r * N_DIM + cc)       = o0;
            *reinterpret_cast<float2*>(out + (size_t)(r + 8) * N_DIM + cc) = o1;
        }
    }
}

// ---------------------------------------------------------------------------
extern "C" void kernel_launch(void* const* d_in, const int* in_sizes, int n_in,
                              void* d_out, int out_size) {
    const float* x    = (const float*)d_in[0];
    const float* wgt  = (const float*)d_in[1];
    const float* bias = (const float*)d_in[2];
    float* out        = (float*)d_out;

    quant_x_kernel<<<(M_DIM * KB) / 8, 256>>>(x);
    quant_w_kernel<<<NB * KB, 256>>>(wgt);

    cudaFuncSetAttribute(gemm_kernel,
                         cudaFuncAttributeMaxDynamicSharedMemorySize, GEMM_SMEM);
    dim3 grid(N_DIM / 128, M_DIM / 128);
    gemm_kernel<<<grid, 256, GEMM_SMEM>>>(bias, out);
}

// round 5
// speedup vs baseline: 2.7338x; 2.5068x over previous
#include <cuda_runtime.h>
#include <cuda_fp16.h>
#include <cstdint>

// Problem shapes (fixed by the dataset)
#define M_DIM 8192
#define K_DIM 4096
#define N_DIM 4096
#define KB    32          // K / 128
#define NB    32          // N / 128

// ---------------------------------------------------------------------------
// Scratch (no cudaMalloc allowed). Quantized values stored as fp16 (ints
// -128..127 are exact in fp16) so the GEMM can use real HMMA hardware.
// ---------------------------------------------------------------------------
__device__ __align__(16) __half g_xq[(size_t)M_DIM * K_DIM];   // 67 MB
__device__ float                g_xs[(size_t)KB * M_DIM];      // 1 MB ([kb][m])
__device__ __align__(16) __half g_wq[(size_t)N_DIM * K_DIM];   // 33.5 MB
__device__ float                g_ws[NB * KB];                 // 4 KB

__device__ __forceinline__ uint32_t h2_bits(__half2 h) {
    return *reinterpret_cast<uint32_t*>(&h);
}

// ---------------------------------------------------------------------------
// Kernel 1: activation quant. One warp per (m, kb) 128-wide block.
// ---------------------------------------------------------------------------
__global__ void quant_x_kernel(const float* __restrict__ x) {
    int gw   = (blockIdx.x * blockDim.x + threadIdx.x) >> 5;
    int lane = threadIdx.x & 31;
    int m  = gw >> 5;
    int kb = gw & 31;

    const float4* p = reinterpret_cast<const float4*>(x + (size_t)m * K_DIM + kb * 128);
    float4 v = p[lane];
    float a = fmaxf(fmaxf(fabsf(v.x), fabsf(v.y)), fmaxf(fabsf(v.z), fabsf(v.w)));
    #pragma unroll
    for (int off = 16; off > 0; off >>= 1)
        a = fmaxf(a, __shfl_xor_sync(0xffffffffu, a, off));

    float s = fmaxf(__fdiv_rn(a, 127.0f), 1e-12f);

    float q0 = fminf(fmaxf(rintf(__fdiv_rn(v.x, s)), -128.0f), 127.0f);
    float q1 = fminf(fmaxf(rintf(__fdiv_rn(v.y, s)), -128.0f), 127.0f);
    float q2 = fminf(fmaxf(rintf(__fdiv_rn(v.z, s)), -128.0f), 127.0f);
    float q3 = fminf(fmaxf(rintf(__fdiv_rn(v.w, s)), -128.0f), 127.0f);

    uint2 h;
    h.x = h2_bits(__floats2half2_rn(q0, q1));
    h.y = h2_bits(__floats2half2_rn(q2, q3));
    reinterpret_cast<uint2*>(g_xq + (size_t)m * K_DIM + kb * 128)[lane] = h;
    if (lane == 0) g_xs[(size_t)kb * M_DIM + m] = s;   // transposed for GEMM reads
}

// ---------------------------------------------------------------------------
// Kernel 2: weight quant. One 256-thread CTA per (nb, kb) 128x128 block.
// ---------------------------------------------------------------------------
__global__ void quant_w_kernel(const float* __restrict__ w) {
    int nb = blockIdx.x >> 5;
    int kb = blockIdx.x & 31;
    int t    = threadIdx.x;
    int row  = t >> 1;
    int half = t & 1;

    const float4* p = reinterpret_cast<const float4*>(
        w + (size_t)(nb * 128 + row) * K_DIM + kb * 128) + half * 16;

    float4 vv[16];
    float a = 0.0f;
    #pragma unroll
    for (int i = 0; i < 16; i++) {
        vv[i] = p[i];
        a = fmaxf(a, fmaxf(fmaxf(fabsf(vv[i].x), fabsf(vv[i].y)),
                           fmaxf(fabsf(vv[i].z), fabsf(vv[i].w))));
    }
    #pragma unroll
    for (int off = 16; off > 0; off >>= 1)
        a = fmaxf(a, __shfl_xor_sync(0xffffffffu, a, off));
    __shared__ float red[8];
    if ((t & 31) == 0) red[t >> 5] = a;
    __syncthreads();
    float am = red[0];
    #pragma unroll
    for (int i = 1; i < 8; i++) am = fmaxf(am, red[i]);

    float s = fmaxf(__fdiv_rn(am, 127.0f), 1e-12f);

    uint2* q = reinterpret_cast<uint2*>(
        g_wq + (size_t)(nb * 128 + row) * K_DIM + kb * 128) + half * 16;
    #pragma unroll
    for (int i = 0; i < 16; i++) {
        float q0 = fminf(fmaxf(rintf(__fdiv_rn(vv[i].x, s)), -128.0f), 127.0f);
        float q1 = fminf(fmaxf(rintf(__fdiv_rn(vv[i].y, s)), -128.0f), 127.0f);
        float q2 = fminf(fmaxf(rintf(__fdiv_rn(vv[i].z, s)), -128.0f), 127.0f);
        float q3 = fminf(fmaxf(rintf(__fdiv_rn(vv[i].w, s)), -128.0f), 127.0f);
        uint2 h;
        h.x = h2_bits(__floats2half2_rn(q0, q1));
        h.y = h2_bits(__floats2half2_rn(q2, q3));
        q[i] = h;
    }
    if (t == 0) g_ws[nb * KB + kb] = s;
}

// ---------------------------------------------------------------------------
// Kernel 3: fp16 GEMM on quantized values (exact: integer values, fp32
// accumulation, per-128-K-block sums < 2^24). 128x128 CTA tile, K-step 128,
// mma.sync.m16n8k16.f32.f16.f16.f32 fed by ldmatrix on swizzled fp16 tiles.
// Per-kb fp32 promotion with combined activation x weight scales.
// ---------------------------------------------------------------------------
#define STAGES     3
#define TILE_BYTES 32768                       // 128 rows x 256 B (fp16)
#define STAGE_SZ   (2 * TILE_BYTES)            // A + B
#define GEMM_SMEM  (STAGES * STAGE_SZ)         // 196608

__device__ __forceinline__ uint32_t smem_u32(const void* p) {
    return (uint32_t)__cvta_generic_to_shared(p);
}
__device__ __forceinline__ void cpa16(uint32_t s, const void* g) {
    asm volatile("cp.async.cg.shared.global [%0], [%1], 16;\n" :: "r"(s), "l"(g));
}
__device__ __forceinline__ void mma_f16(float c[4], const uint32_t a[4],
                                        uint32_t b0, uint32_t b1) {
    asm volatile(
        "mma.sync.aligned.m16n8k16.row.col.f32.f16.f16.f32 "
        "{%0,%1,%2,%3}, {%4,%5,%6,%7}, {%8,%9}, {%0,%1,%2,%3};\n"
        : "+f"(c[0]), "+f"(c[1]), "+f"(c[2]), "+f"(c[3])
        : "r"(a[0]), "r"(a[1]), "r"(a[2]), "r"(a[3]), "r"(b0), "r"(b1));
}
__device__ __forceinline__ void ldsm4(uint32_t r[4], uint32_t addr) {
    asm volatile("ldmatrix.sync.aligned.m8n8.x4.shared.b16 {%0,%1,%2,%3}, [%4];"
                 : "=r"(r[0]), "=r"(r[1]), "=r"(r[2]), "=r"(r[3]) : "r"(addr));
}

__global__ void __launch_bounds__(256, 1)
gemm_kernel(const float* __restrict__ bias, float* __restrict__ out) {
    extern __shared__ __align__(1024) char smem[];
    const uint32_t sb = smem_u32(smem);
    const int tid  = threadIdx.x;
    const int lane = tid & 31;
    const int w    = tid >> 5;
    const int m0 = blockIdx.y * 128;
    const int n0 = blockIdx.x * 128;
    const int nb = blockIdx.x;
    const int wm   = w & 3;        // 4 warps along M (32 rows each)
    const int wn   = w >> 2;       // 2 warps along N (64 cols each)
    const int grp  = lane >> 2;    // 0..7
    const int tig  = lane & 3;     // 0..3
    const int j    = lane >> 3;    // ldmatrix matrix index 0..3
    const int rlo  = lane & 7;     // ldmatrix row-in-matrix

    // tile loader: A + B, 128 rows x 256B each, chunk-swizzled (16B chunks,
    // low-3 bits of chunk index XOR row&7 -> conflict-free ldmatrix reads)
    auto load_stage = [&](int stage, int kb) {
        const __half* Ag = g_xq + (size_t)m0 * K_DIM + kb * 128;
        const __half* Bg = g_wq + (size_t)n0 * K_DIM + kb * 128;
        uint32_t As = sb + stage * STAGE_SZ;
        uint32_t Bs = As + TILE_BYTES;
        #pragma unroll
        for (int i = 0; i < 8; i++) {
            int id = i * 256 + tid;        // 0..2047 chunks of 16B
            int r  = id >> 4;              // row 0..127
            int c  = id & 15;              // chunk 0..15
            uint32_t so = r * 256 + (((c & 8) | ((c ^ r) & 7)) << 4);
            cpa16(As + so, Ag + (size_t)r * K_DIM + c * 8);
            cpa16(Bs + so, Bg + (size_t)r * K_DIM + c * 8);
        }
    };

    float facc[2][8][4];
    #pragma unroll
    for (int i = 0; i < 2; i++)
        #pragma unroll
        for (int jj = 0; jj < 8; jj++)
            #pragma unroll
            for (int k = 0; k < 4; k++) facc[i][jj][k] = 0.0f;

    load_stage(0, 0); asm volatile("cp.async.commit_group;");
    load_stage(1, 1); asm volatile("cp.async.commit_group;");

    // precomputed ldmatrix base offsets (within a stage)
    const int arow = wm * 32 + (j & 1) * 8 + rlo;            // + fm*16
    const int brow = wn * 64 + ((j >> 1) << 3) + rlo;        // + fnp*16

    for (int kb = 0; kb < KB; kb++) {
        asm volatile("cp.async.wait_group 1;");
        __syncthreads();
        const uint32_t As = sb + (uint32_t)(kb % 3) * STAGE_SZ;
        const uint32_t Bs = As + TILE_BYTES;

        // per-kb combined scales for this thread's 4 output rows
        const float wsv = g_ws[nb * KB + kb];
        float csv[2][2];
        #pragma unroll
        for (int fm = 0; fm < 2; fm++) {
            int r = m0 + wm * 32 + fm * 16 + grp;
            csv[fm][0] = __ldg(&g_xs[(size_t)kb * M_DIM + r])     * wsv;
            csv[fm][1] = __ldg(&g_xs[(size_t)kb * M_DIM + r + 8]) * wsv;
        }

        float c[2][8][4];
        #pragma unroll
        for (int i = 0; i < 2; i++)
            #pragma unroll
            for (int jj = 0; jj < 8; jj++)
                #pragma unroll
                for (int k = 0; k < 4; k++) c[i][jj][k] = 0.0f;

        #pragma unroll
        for (int kk = 0; kk < 8; kk++) {
            // A fragments: 2 x ldmatrix.x4 (m16k16 each)
            uint32_t a[2][4];
            #pragma unroll
            for (int fm = 0; fm < 2; fm++) {
                int row   = arow + fm * 16;
                int chunk = kk * 2 + (j >> 1);
                ldsm4(a[fm], As + row * 256 + (((chunk & 8) | ((chunk ^ row) & 7)) << 4));
            }
            // B fragments + MMAs: 4 x ldmatrix.x4 (two n8k16 frags each)
            #pragma unroll
            for (int fnp = 0; fnp < 4; fnp++) {
                int row   = brow + fnp * 16;
                int chunk = kk * 2 + (j & 1);
                uint32_t bf[4];
                ldsm4(bf, Bs + row * 256 + (((chunk & 8) | ((chunk ^ row) & 7)) << 4));
                #pragma unroll
                for (int fm = 0; fm < 2; fm++) {
                    mma_f16(c[fm][fnp * 2],     a[fm], bf[0], bf[1]);
                    mma_f16(c[fm][fnp * 2 + 1], a[fm], bf[2], bf[3]);
                }
            }
        }

        // exact per-kb promotion (c holds exact integer-valued fp32 sums)
        #pragma unroll
        for (int fm = 0; fm < 2; fm++)
            #pragma unroll
            for (int fn = 0; fn < 8; fn++) {
                facc[fm][fn][0] = fmaf(csv[fm][0], c[fm][fn][0], facc[fm][fn][0]);
                facc[fm][fn][1] = fmaf(csv[fm][0], c[fm][fn][1], facc[fm][fn][1]);
                facc[fm][fn][2] = fmaf(csv[fm][1], c[fm][fn][2], facc[fm][fn][2]);
                facc[fm][fn][3] = fmaf(csv[fm][1], c[fm][fn][3], facc[fm][fn][3]);
            }

        if (kb + 2 < KB) load_stage((kb + 2) % 3, kb + 2);
        asm volatile("cp.async.commit_group;");
    }

    // epilogue: add bias, store fp32
    #pragma unroll
    for (int fm = 0; fm < 2; fm++) {
        int r = m0 + wm * 32 + fm * 16 + grp;
        #pragma unroll
        for (int fn = 0; fn < 8; fn++) {
            int cc = n0 + wn * 64 + fn * 8 + tig * 2;
            float2 b2 = *reinterpret_cast<const float2*>(bias + cc);
            float2 o0, o1;
            o0.x = facc[fm][fn][0] + b2.x;
            o0.y = facc[fm][fn][1] + b2.y;
            o1.x = facc[fm][fn][2] + b2.x;
            o1.y = facc[fm][fn][3] + b2.y;
            *reinterpret_cast<float2*>(out + (size_t)r * N_DIM + cc)       = o0;
            *reinterpret_cast<float2*>(out + (size_t)(r + 8) * N_DIM + cc) = o1;
        }
    }
}

// ---------------------------------------------------------------------------
extern "C" void kernel_launch(void* const* d_in, const int* in_sizes, int n_in,
                              void* d_out, int out_size) {
    const float* x    = (const float*)d_in[0];
    const float* wgt  = (const float*)d_in[1];
    const float* bias = (const float*)d_in[2];
    float* out        = (float*)d_out;

    quant_x_kernel<<<(M_DIM * KB) / 8, 256>>>(x);
    quant_w_kernel<<<NB * KB, 256>>>(wgt);

    cudaFuncSetAttribute(gemm_kernel,
                         cudaFuncAttributeMaxDynamicSharedMemorySize, GEMM_SMEM);
    dim3 grid(N_DIM / 128, M_DIM / 128);
    gemm_kernel<<<grid, 256, GEMM_SMEM>>>(bias, out);
}